// round 17
// baseline (speedup 1.0000x reference)
#include <cuda_runtime.h>
#include <cuda_fp16.h>
#include <cstdint>
#include <math.h>

// ---------------------------------------------------------------------------
// Problem dims
#define BB   4096
#define DD   1024
#define RB   2048
#define GN   (3*RB)     // 6144
#define MAXD 2560

// Tile counts
#define NGTILES 3072    // gates tiles (32 m-blocks x 96 n-blocks)
#define NZTILES 1024    // z tiles (32 m-blocks x 32 n-blocks)
#define NTILES  (NGTILES + NZTILES)

// ---------------------------------------------------------------------------
// Device-global scratch
__device__ __half g_X0[(size_t)BB*DD],  g_X1[(size_t)BB*DD];
__device__ __half g_P0[(size_t)BB*RB],  g_P1[(size_t)BB*RB];
__device__ __half g_Wi0[(size_t)RB*DD], g_Wi1[(size_t)RB*DD];
__device__ __half g_Wr0[(size_t)RB*RB], g_Wr1[(size_t)RB*RB];
__device__ __half g_Wg0[(size_t)GN*DD], g_Wg1[(size_t)GN*DD];
__device__ float g_G[(size_t)BB*GN];    // sigmoid(gates)
__device__ int   g_cnt;                 // completed gates tiles

// ---------------------------------------------------------------------------
// Tiling: CTA 128x64, 256 threads (8 warps, warp tile 32x32), BK=64,
// 2-stage double buffer -> 96KB smem -> 2 CTAs/SM.
#define BK           64
#define A_TILE_BYTES (128 * 128)
#define B_TILE_BYTES (64 * 128)
#define STAGE_BYTES  (2*A_TILE_BYTES + 2*B_TILE_BYTES)   // 49152 B
#define B_OFF        (2*A_TILE_BYTES)
#define SMEM_SIZE    (2 * STAGE_BYTES)                    // 98304 B

__device__ __forceinline__ uint32_t smem_to_u32(const void* p) {
    uint32_t a;
    asm("{ .reg .u64 t; cvta.to.shared.u64 t, %1; cvt.u32.u64 %0, t; }" : "=r"(a) : "l"(p));
    return a;
}

__device__ __forceinline__ void ldsm_x4(uint32_t (&r)[4], uint32_t addr) {
    asm volatile("ldmatrix.sync.aligned.m8n8.x4.shared.b16 {%0,%1,%2,%3}, [%4];"
                 : "=r"(r[0]), "=r"(r[1]), "=r"(r[2]), "=r"(r[3]) : "r"(addr));
}

__device__ __forceinline__ void mma_f16(float (&c)[4], const uint32_t (&a)[4],
                                        const uint32_t* b) {
    asm volatile("mma.sync.aligned.m16n8k16.row.col.f32.f16.f16.f32 "
                 "{%0,%1,%2,%3}, {%4,%5,%6,%7}, {%8,%9}, {%0,%1,%2,%3};"
                 : "+f"(c[0]), "+f"(c[1]), "+f"(c[2]), "+f"(c[3])
                 : "r"(a[0]), "r"(a[1]), "r"(a[2]), "r"(a[3]), "r"(b[0]), "r"(b[1]));
}

template<int ROWS>
__device__ __forceinline__ void cp_tile(uint32_t sm_tile, const __half* __restrict__ g,
                                        int ld, int tid) {
    constexpr int CHUNKS = ROWS * 8;
    #pragma unroll
    for (int i = 0; i < CHUNKS / 256; ++i) {
        int c   = tid + (i << 8);
        int row = c >> 3;
        int ch  = c & 7;
        uint32_t off = (uint32_t)((row << 7) | (((ch ^ (row & 7))) << 4));
        const void* gp = g + (size_t)row * ld + (ch << 3);
        asm volatile("cp.async.cg.shared.global [%0], [%1], 16;"
                     :: "r"(sm_tile + off), "l"(gp));
    }
}
#define CP_COMMIT()  asm volatile("cp.async.commit_group;" ::: "memory")
#define CP_WAIT(n)   asm volatile("cp.async.wait_group %0;" :: "n"(n) : "memory")

// ---------------------------------------------------------------------------
__device__ __forceinline__ void load_afr(uint32_t sTile, int lane, int wm, int ks,
                                         uint32_t (&afr)[2][4]) {
    int r  = wm + (((lane >> 3) & 1) << 3) + (lane & 7);
    int kc = (ks << 1) + (lane >> 4);
    #pragma unroll
    for (int mi = 0; mi < 2; ++mi) {
        int rr = r + mi * 16;
        uint32_t addr = (uint32_t)((rr << 7) | (((kc ^ (rr & 7))) << 4));
        ldsm_x4(afr[mi], sTile + addr);
    }
}

__device__ __forceinline__ void do_product(float (&acc)[2][4][4],
                                           const uint32_t (&afr)[2][4],
                                           const uint32_t (&bfr)[2][4]) {
    #pragma unroll
    for (int mi = 0; mi < 2; ++mi)
        #pragma unroll
        for (int nj = 0; nj < 4; ++nj)
            mma_f16(acc[mi][nj], afr[mi], &bfr[nj >> 1][(nj & 1) << 1]);
}

// One BK=64 window: 3 split-products, magnitude-ordered accumulation.
__device__ __forceinline__ void compute_stage(uint32_t st, int lane, int wm, int wn,
                                              float (&accL)[2][4][4],
                                              float (&accS)[2][4][4])
{
    uint32_t sA = st;
    uint32_t sB = st + B_OFF;
    #pragma unroll
    for (int ks = 0; ks < 4; ++ks) {
        uint32_t bfr[2][2][4];
        {
            int r  = wn + (((lane >> 4) & 1) << 3) + (lane & 7);
            int kc = (ks << 1) + ((lane >> 3) & 1);
            #pragma unroll
            for (int nj2 = 0; nj2 < 2; ++nj2) {
                int rr = r + nj2 * 16;
                uint32_t addr = (uint32_t)((rr << 7) | (((kc ^ (rr & 7))) << 4));
                #pragma unroll
                for (int s = 0; s < 2; ++s)
                    ldsm_x4(bfr[s][nj2], sB + s * B_TILE_BYTES + addr);
            }
        }
        {
            uint32_t afr[2][4];
            load_afr(sA + 0 * A_TILE_BYTES, lane, wm, ks, afr);
            do_product(accL, afr, bfr[0]);
            do_product(accS, afr, bfr[1]);
        }
        {
            uint32_t afr[2][4];
            load_afr(sA + 1 * A_TILE_BYTES, lane, wm, ks, afr);
            do_product(accS, afr, bfr[0]);
        }
    }
}

// ---------------------------------------------------------------------------
// Issue one window of tile t into stage st. Gates tiles: t < NGTILES (16 win);
// z tiles: t >= NGTILES (48 win: 16 X*Wi then 32 P*Wr).
__device__ __forceinline__ void issue_win(int t, int w, uint32_t st, int tid)
{
    if (t < NGTILES) {
        int bm = (t / 96) * 128;
        int bn = (t % 96) * 64;
        size_t koff = (size_t)w * BK;
        cp_tile<128>(st + 0 * A_TILE_BYTES, g_X0 + (size_t)bm * DD + koff, DD, tid);
        cp_tile<128>(st + 1 * A_TILE_BYTES, g_X1 + (size_t)bm * DD + koff, DD, tid);
        cp_tile< 64>(st + B_OFF + 0 * B_TILE_BYTES, g_Wg0 + (size_t)bn * DD + koff, DD, tid);
        cp_tile< 64>(st + B_OFF + 1 * B_TILE_BYTES, g_Wg1 + (size_t)bn * DD + koff, DD, tid);
    } else {
        int zt = t - NGTILES;
        int bm = (zt >> 5) * 128;
        int bn = (zt & 31) * 64;
        if (w < DD / BK) {
            size_t koff = (size_t)w * BK;
            cp_tile<128>(st + 0 * A_TILE_BYTES, g_X0 + (size_t)bm * DD + koff, DD, tid);
            cp_tile<128>(st + 1 * A_TILE_BYTES, g_X1 + (size_t)bm * DD + koff, DD, tid);
            cp_tile< 64>(st + B_OFF + 0 * B_TILE_BYTES, g_Wi0 + (size_t)bn * DD + koff, DD, tid);
            cp_tile< 64>(st + B_OFF + 1 * B_TILE_BYTES, g_Wi1 + (size_t)bn * DD + koff, DD, tid);
        } else {
            size_t koff = (size_t)(w - DD / BK) * BK;
            cp_tile<128>(st + 0 * A_TILE_BYTES, g_P0 + (size_t)bm * RB + koff, RB, tid);
            cp_tile<128>(st + 1 * A_TILE_BYTES, g_P1 + (size_t)bm * RB + koff, RB, tid);
            cp_tile< 64>(st + B_OFF + 0 * B_TILE_BYTES, g_Wr0 + (size_t)bn * RB + koff, RB, tid);
            cp_tile< 64>(st + B_OFF + 1 * B_TILE_BYTES, g_Wr1 + (size_t)bn * RB + koff, RB, tid);
        }
    }
    CP_COMMIT();
}

#define ZERO_ACC2(aL, aS) do { \
    _Pragma("unroll") for (int _i = 0; _i < 2; ++_i) \
    _Pragma("unroll") for (int _j = 0; _j < 4; ++_j) \
    _Pragma("unroll") for (int _l = 0; _l < 4; ++_l) { (aL)[_i][_j][_l] = 0.0f; (aS)[_i][_j][_l] = 0.0f; } \
} while (0)

// ---------------------------------------------------------------------------
// Persistent fused kernel: all resident CTAs stride over 4096 tiles with a
// continuous cross-tile window pipeline. Gates tiles release g_cnt; z tiles'
// epilogues acquire it before reading g_G.
__global__ __launch_bounds__(256, 2) void gemm_persistent_kernel(
    const float* __restrict__ Praw, float* __restrict__ out)
{
    extern __shared__ char smem[];
    uint32_t sb = smem_to_u32(smem);
    int tid  = threadIdx.x;
    int lane = tid & 31;
    int wid  = tid >> 5;
    int wm   = (wid >> 1) * 32;
    int wn   = (wid & 1) * 32;
    int G    = gridDim.x;

    int iw = 0;   // global issued/computed window parity counter

    int t = blockIdx.x;
    if (t < NTILES) issue_win(t, 0, sb + ((iw & 1) * STAGE_BYTES), tid);

    while (t < NTILES) {
        const int NW = (t < NGTILES) ? (DD / BK) : ((DD + RB) / BK);
        float accL[2][4][4], accS[2][4][4];
        ZERO_ACC2(accL, accS);

        for (int w = 0; w < NW; ++w) {
            CP_WAIT(0);                 // the single in-flight group (window w)
            __syncthreads();
            // issue next window (1-ahead), crossing tile boundary seamlessly
            if (w + 1 < NW) {
                issue_win(t, w + 1, sb + (((iw + 1) & 1) * STAGE_BYTES), tid);
            } else {
                int tn = t + G;
                if (tn < NTILES) issue_win(tn, 0, sb + (((iw + 1) & 1) * STAGE_BYTES), tid);
            }
            compute_stage(sb + ((iw & 1) * STAGE_BYTES), lane, wm, wn, accL, accS);
            ++iw;
        }

        // ---- Epilogue ----
        if (t < NGTILES) {
            int bm = (t / 96) * 128;
            int bn = (t % 96) * 64;
            int rbase = bm + wm + (lane >> 2);
            int cbase = bn + wn + ((lane & 3) << 1);
            #pragma unroll
            for (int mi = 0; mi < 2; ++mi) {
                #pragma unroll
                for (int nj = 0; nj < 4; ++nj) {
                    int r0 = rbase + mi * 16;
                    int c0 = cbase + nj * 8;
                    float v0 = 1.0f / (1.0f + expf(-(accL[mi][nj][0] + accS[mi][nj][0])));
                    float v1 = 1.0f / (1.0f + expf(-(accL[mi][nj][1] + accS[mi][nj][1])));
                    float v2 = 1.0f / (1.0f + expf(-(accL[mi][nj][2] + accS[mi][nj][2])));
                    float v3 = 1.0f / (1.0f + expf(-(accL[mi][nj][3] + accS[mi][nj][3])));
                    *reinterpret_cast<float2*>(g_G + (size_t)r0 * GN + c0)       = make_float2(v0, v1);
                    *reinterpret_cast<float2*>(g_G + (size_t)(r0 + 8) * GN + c0) = make_float2(v2, v3);
                }
            }
            // Release: stores visible, then count this tile.
            __threadfence();
            __syncthreads();
            if (tid == 0) atomicAdd(&g_cnt, 1);
        } else {
            // Acquire: all gates tiles must be complete before reading g_G.
            if (tid == 0) {
                volatile int* c = &g_cnt;
                while (*c < NGTILES) { }
            }
            __syncthreads();
            __threadfence();

            int zt = t - NGTILES;
            int bm = (zt >> 5) * 128;
            int bn = (zt & 31) * 64;
            int rbase = bm + wm + (lane >> 2);
            int cbase = bn + wn + ((lane & 3) << 1);
            #pragma unroll
            for (int mi = 0; mi < 2; ++mi) {
                #pragma unroll
                for (int nj = 0; nj < 4; ++nj) {
                    int r0 = rbase + mi * 16;
                    int c0 = cbase + nj * 8;
                    #pragma unroll
                    for (int half = 0; half < 2; ++half) {
                        int r = r0 + half * 8;
                        float z0 = accL[mi][nj][half*2+0] + accS[mi][nj][half*2+0];
                        float z1 = accL[mi][nj][half*2+1] + accS[mi][nj][half*2+1];
                        const float* grow = g_G + (size_t)r * GN;
                        float gi0 = __ldcg(grow + c0),          gi1 = __ldcg(grow + c0 + 1);
                        float gf0 = __ldcg(grow + RB + c0),     gf1 = __ldcg(grow + RB + c0 + 1);
                        float go0 = __ldcg(grow + 2*RB + c0),   go1 = __ldcg(grow + 2*RB + c0 + 1);
                        float2 p  = *reinterpret_cast<const float2*>(Praw + (size_t)r * MAXD + c0);
                        float s0 = 0.9f * (gf0 * p.x) + 0.1f * tanhf(gi0 * z0);
                        float s1 = 0.9f * (gf1 * p.y) + 0.1f * tanhf(gi1 * z1);
                        s0 = go0 * s0;
                        s1 = go1 * s1;
                        if (s0 > 0.5f) s0 -= 0.5f;
                        if (s1 > 0.5f) s1 -= 0.5f;
                        *reinterpret_cast<float2*>(out + (size_t)r * MAXD + c0) = make_float2(s0, s1);
                    }
                }
            }
        }
        t += G;
    }
}

// ---------------------------------------------------------------------------
// Fused fp32 -> 2x fp16 split kernel + pad zeroing + g_cnt reset.
#define S_X    ((size_t)BB*DD/4)
#define S_P    ((size_t)BB*RB/4)
#define S_WI   ((size_t)RB*DD/4)
#define S_WR   ((size_t)RB*RB/4)
#define S_WG   ((size_t)GN*DD/4)
#define S_TOT  (S_X + S_P + S_WI + S_WR + S_WG)
#define S_PAD  ((size_t)BB*(MAXD-RB)/4)
#define S_ALL  (S_TOT + S_PAD)

__device__ __forceinline__ void split_store(const float4 v, __half* d0, __half* d1, size_t o)
{
    float a[4] = {v.x, v.y, v.z, v.w};
    __half h0[4], h1[4];
    #pragma unroll
    for (int i = 0; i < 4; ++i) {
        h0[i] = __float2half_rn(a[i]);
        float r = a[i] - __half2float(h0[i]);
        h1[i] = __float2half_rn(r);
    }
    *reinterpret_cast<uint2*>(d0 + o) = *reinterpret_cast<uint2*>(h0);
    *reinterpret_cast<uint2*>(d1 + o) = *reinterpret_cast<uint2*>(h1);
}

__global__ void split_all_kernel(const float* __restrict__ X, const float* __restrict__ P,
                                 const float* __restrict__ Wi, const float* __restrict__ Wr,
                                 const float* __restrict__ Wg, float* __restrict__ out)
{
    size_t i4 = (size_t)blockIdx.x * blockDim.x + threadIdx.x;
    if (i4 == 0) g_cnt = 0;                  // reset gates-complete counter
    if (i4 >= S_ALL) return;

    if (i4 >= S_TOT) {                       // pad region: out[:, 2048:2560] = 0
        size_t idx = i4 - S_TOT;
        int perrow = (MAXD - RB) / 4;
        int row = (int)(idx / perrow);
        int c4  = (int)(idx % perrow);
        *reinterpret_cast<float4*>(out + (size_t)row * MAXD + RB + c4 * 4) =
            make_float4(0.0f, 0.0f, 0.0f, 0.0f);
        return;
    }

    const float* src; __half *d0, *d1; size_t e; int cols, srcld;
    if (i4 < S_X) {
        src = X;  d0 = g_X0;  d1 = g_X1;  e = i4 * 4;            cols = DD; srcld = DD;
    } else if (i4 < S_X + S_P) {
        src = P;  d0 = g_P0;  d1 = g_P1;  e = (i4 - S_X) * 4;    cols = RB; srcld = MAXD;
    } else if (i4 < S_X + S_P + S_WI) {
        src = Wi; d0 = g_Wi0; d1 = g_Wi1; e = (i4 - S_X - S_P) * 4; cols = DD; srcld = DD;
    } else if (i4 < S_X + S_P + S_WI + S_WR) {
        src = Wr; d0 = g_Wr0; d1 = g_Wr1; e = (i4 - S_X - S_P - S_WI) * 4; cols = RB; srcld = RB;
    } else {
        src = Wg; d0 = g_Wg0; d1 = g_Wg1; e = (i4 - S_X - S_P - S_WI - S_WR) * 4; cols = DD; srcld = DD;
    }
    int row = (int)(e / cols);
    int col = (int)(e % cols);
    float4 v = *reinterpret_cast<const float4*>(src + (size_t)row * srcld + col);
    split_store(v, d0, d1, e);
}

// ---------------------------------------------------------------------------
extern "C" void kernel_launch(void* const* d_in, const int* in_sizes, int n_in,
                              void* d_out, int out_size)
{
    const float* X    = (const float*)d_in[0];
    const float* P    = (const float*)d_in[1];
    const float* Win  = (const float*)d_in[2];
    const float* Wres = (const float*)d_in[3];
    const float* Wg   = (const float*)d_in[4];
    float* out = (float*)d_out;

    static int nblocks = 0;
    if (nblocks == 0) {
        cudaFuncSetAttribute(gemm_persistent_kernel,
                             cudaFuncAttributeMaxDynamicSharedMemorySize, SMEM_SIZE);
        int sms = 148;
        cudaDeviceGetAttribute(&sms, cudaDevAttrMultiProcessorCount, 0);
        nblocks = 2 * sms;                   // all co-resident (2 CTAs/SM)
    }

    split_all_kernel<<<(int)((S_ALL + 255) / 256), 256>>>(X, P, Win, Wres, Wg, out);
    gemm_persistent_kernel<<<nblocks, 256, SMEM_SIZE>>>(P, out);
}